// round 12
// baseline (speedup 1.0000x reference)
#include <cuda_runtime.h>
#include <cuda_fp16.h>
#include <cstdint>

#define BATCH 1024
#define CIN   512
#define HW    49
#define KDIM  2304          // 9 * 256
#define MDIM  50176         // 1024 * 49
#define NDIM  512

// Scratch (module-load allocation; legal per harness rules)
// G[b][j][n][w][l]: folded two-group shifted sum; l innermost (256 halfs = 512B rows)
__device__ __align__(16) __half G_g[(size_t)BATCH * 3 * HW * 256];   // 77 MB
__device__ __align__(16) __half Whn_g[(size_t)NDIM * KDIM];          // [i][kk] K-major

// ---------------------------------------------------------------------------
// helpers
// ---------------------------------------------------------------------------
__device__ __forceinline__ uint32_t s2u(const void* p) {
    uint32_t a;
    asm("{ .reg .u64 t; cvta.to.shared.u64 t, %1; cvt.u32.u64 %0, t; }" : "=r"(a) : "l"(p));
    return a;
}
__device__ __forceinline__ uint32_t swz(uint32_t o) { return o ^ ((o >> 3) & 0x70); }

// ---------------------------------------------------------------------------
// Phase 1 (merged): blocks [0, 2048) build G; blocks [2048, 2336) transpose W.
// (unchanged from R9/R10)
// ---------------------------------------------------------------------------
#define XP2 260
#define GWORK (3 * HW * 16)   // 2352 items per prep_g block

__global__ __launch_bounds__(512, 2) void prep(const float* __restrict__ x,
                                               const float* __restrict__ W) {
    extern __shared__ float sm[];

    if (blockIdx.x < 2 * BATCH) {
        const int b    = blockIdx.x >> 1;
        const int half = blockIdx.x & 1;
        const float* xb = x + (size_t)b * CIN * HW;

        for (int i = threadIdx.x; i < 256 * HW; i += blockDim.x) {
            int cc = i / HW;
            int hw = i - cc * HW;
            int c  = (cc < 128) ? (half * 128 + cc) : (128 + half * 128 + cc);
            sm[hw * XP2 + cc] = xb[c * HW + hw];
        }
        __syncthreads();

        uint4* gout = (uint4*)(G_g + (size_t)b * 3 * HW * 256);

        for (int base = threadIdx.x; base < GWORK; base += 1024) {
            int idx0 = base;
            int idx1 = base + 512;
            const bool has1 = (idx1 < GWORK);

            int l8_0 = idx0 & 15,  rr0 = idx0 >> 4;
            int l8_1 = idx1 & 15,  rr1 = idx1 >> 4;

            int j0 = rr0 / 49, nw0 = rr0 - j0 * 49, n0 = nw0 / 7, w0 = nw0 - 7 * n0;
            int j1 = rr1 / 49, nw1 = rr1 - j1 * 49, n1 = nw1 / 7, w1 = nw1 - 7 * n1;

            int hb0 = n0 + j0 - 1, ha0 = ((n0 + 6) % 7) + j0 - 1;
            int hb1 = n1 + j1 - 1, ha1 = ((n1 + 6) % 7) + j1 - 1;
            bool bv0 = (hb0 >= 0) && (hb0 < 7), av0 = (ha0 >= 0) && (ha0 < 7);
            bool bv1 = has1 && (hb1 >= 0) && (hb1 < 7);
            bool av1 = has1 && (ha1 >= 0) && (ha1 < 7);

            const float4* pa0 = (const float4*)(sm + (ha0 * 7 + w0) * XP2 + 128 + l8_0 * 8);
            const float4* pb0 = (const float4*)(sm + (hb0 * 7 + w0) * XP2 + l8_0 * 8);
            const float4* pa1 = (const float4*)(sm + (ha1 * 7 + w1) * XP2 + 128 + l8_1 * 8);
            const float4* pb1 = (const float4*)(sm + (hb1 * 7 + w1) * XP2 + l8_1 * 8);

            float4 a00 = {0,0,0,0}, a01 = {0,0,0,0}, b00 = {0,0,0,0}, b01 = {0,0,0,0};
            float4 a10 = {0,0,0,0}, a11 = {0,0,0,0}, b10 = {0,0,0,0}, b11 = {0,0,0,0};
            if (av0) { a00 = pa0[0]; a01 = pa0[1]; }
            if (bv0) { b00 = pb0[0]; b01 = pb0[1]; }
            if (av1) { a10 = pa1[0]; a11 = pa1[1]; }
            if (bv1) { b10 = pb1[0]; b11 = pb1[1]; }

            {
                __half2 p0 = __floats2half2_rn(a00.x + b00.x, a00.y + b00.y);
                __half2 p1 = __floats2half2_rn(a00.z + b00.z, a00.w + b00.w);
                __half2 p2 = __floats2half2_rn(a01.x + b01.x, a01.y + b01.y);
                __half2 p3 = __floats2half2_rn(a01.z + b01.z, a01.w + b01.w);
                uint4 o;
                o.x = *reinterpret_cast<uint32_t*>(&p0);
                o.y = *reinterpret_cast<uint32_t*>(&p1);
                o.z = *reinterpret_cast<uint32_t*>(&p2);
                o.w = *reinterpret_cast<uint32_t*>(&p3);
                gout[rr0 * 32 + half * 16 + l8_0] = o;
            }
            if (has1) {
                __half2 p0 = __floats2half2_rn(a10.x + b10.x, a10.y + b10.y);
                __half2 p1 = __floats2half2_rn(a10.z + b10.z, a10.w + b10.w);
                __half2 p2 = __floats2half2_rn(a11.x + b11.x, a11.y + b11.y);
                __half2 p3 = __floats2half2_rn(a11.z + b11.z, a11.w + b11.w);
                uint4 o;
                o.x = *reinterpret_cast<uint32_t*>(&p0);
                o.y = *reinterpret_cast<uint32_t*>(&p1);
                o.z = *reinterpret_cast<uint32_t*>(&p2);
                o.w = *reinterpret_cast<uint32_t*>(&p3);
                gout[rr1 * 32 + half * 16 + l8_1] = o;
            }
        }
    } else {
        float* tile = sm;                       // [64][65]
        const int bid2 = blockIdx.x - 2 * BATCH;   // 0..287
        const int jk = bid2 / 32;
        const int r  = bid2 - jk * 32;
        const int lt = r >> 3;
        const int it = r & 7;

        for (int i = threadIdx.x; i < 64 * 64; i += blockDim.x) {
            int ll = i >> 6, ii = i & 63;
            tile[ll * 65 + ii] = W[((size_t)(lt * 64 + ll) * 9 + jk) * NDIM + it * 64 + ii];
        }
        __syncthreads();

        __half2* out2 = (__half2*)Whn_g;
        for (int i = threadIdx.x; i < 64 * 32; i += blockDim.x) {
            int ii = i >> 5, l2 = i & 31;
            float v0 = tile[(l2 * 2) * 65 + ii];
            float v1 = tile[(l2 * 2 + 1) * 65 + ii];
            out2[(size_t)(it * 64 + ii) * (KDIM / 2) + jk * 128 + lt * 32 + l2] =
                __floats2half2_rn(v0, v1);
        }
    }
}

// ---------------------------------------------------------------------------
// Phase 2: fused-im2col GEMM  out[m][i] = sum_k A[m][k] * Whn[i][k]
// NEW: 512 threads / 16 warps (4x4 grid), warp tile 32x32 -> ~80 regs/thread,
// 4 warps per SMSP for latency hiding. Tiles/smem/loads otherwise identical.
// ---------------------------------------------------------------------------
#define BK 64
#define NC (KDIM / BK)        // 36
#define STG_H 8192            // halfs per stage per operand (128 * 64)
#define DSMEM (3 * 2 * STG_H * 2 + 256)

struct ARow {
    const __half* g[2];   // per q: G base for this row (b,n and c*8 folded in)
    int p[2];
};

__device__ __forceinline__ void load_stage(
    const ARow& ar, const __half* __restrict__ Bg,
    uint32_t sA, uint32_t sB, int chunk, int tid)
{
    const int jk = chunk >> 2;
    const int l0 = (chunk & 3) << 6;
    const int j  = (jk * 11) >> 5;        // jk/3 for jk in [0,8]
    const int k  = jk - 3 * j;
    const int off0 = j * (49 * 256) + l0;
    const int r0 = tid >> 3;              // 0..63
    const int c16 = (tid & 7) * 16;
#pragma unroll
    for (int q = 0; q < 2; q++) {         // A: 128 rows x 8 chunks of 16B (1024 total)
        const int p = ar.p[q];
        int w2 = p + k + 5; if (w2 >= 7) w2 -= 7;
        const uint32_t vsz = ((unsigned)(p + k - 1) <= 6u) ? 16u : 0u;
        const uint32_t dst = sA + swz((uint32_t)((r0 + q * 64) * 128 + c16));
        const __half* src = ar.g[q] + off0 + w2 * 256;
        asm volatile("cp.async.cg.shared.global [%0], [%1], 16, %2;"
                     :: "r"(dst), "l"(src), "r"(vsz));
    }
    const int k0 = chunk * BK;
#pragma unroll
    for (int q = 0; q < 2; q++) {         // B: 1024 x 16B
        int id = tid + q * 512;
        int r = id >> 3, c = id & 7;
        asm volatile("cp.async.cg.shared.global [%0], [%1], 16;"
                     :: "r"(sB + swz((uint32_t)(r * 128 + c * 16))),
                        "l"(Bg + (size_t)r * KDIM + k0 + c * 8));
    }
    asm volatile("cp.async.commit_group;" ::: "memory");
}

__global__ __launch_bounds__(512, 1) void gemm_f16(float* __restrict__ out) {
    extern __shared__ char dsm[];
    const uint32_t sbase = (s2u(dsm) + 127) & ~127u;

    const int bn   = blockIdx.x;     // 0..3
    const int bm   = blockIdx.y;     // 0..391
    const int tid  = threadIdx.x;
    const int wid  = tid >> 5;
    const int lane = tid & 31;
    const int wm   = wid >> 2;       // 0..3  (32-row slab)
    const int wn   = wid & 3;        // 0..3  (32-col slab)

    const __half* Bg = Whn_g + (size_t)bn * 128 * KDIM;

    ARow ar;
    {
        const int r0 = tid >> 3;
        const int c8 = (tid & 7) * 8;
#pragma unroll
        for (int q = 0; q < 2; q++) {
            int m  = bm * 128 + r0 + q * 64;
            int b  = m / 49;
            int np = m - b * 49;
            int n  = np / 7;
            ar.p[q] = np - 7 * n;
            ar.g[q] = G_g + ((size_t)b * 147 + n * 7) * 256 + c8;
        }
    }

    uint32_t sA[3], sB[3];
#pragma unroll
    for (int s = 0; s < 3; s++) {
        sA[s] = sbase + s * (STG_H * 2);
        sB[s] = sbase + (3 + s) * (STG_H * 2);
    }

    float acc[2][4][4];
#pragma unroll
    for (int a = 0; a < 2; a++)
#pragma unroll
        for (int b = 0; b < 4; b++)
#pragma unroll
            for (int c = 0; c < 4; c++) acc[a][b][c] = 0.f;

    load_stage(ar, Bg, sA[0], sB[0], 0, tid);
    load_stage(ar, Bg, sA[1], sB[1], 1, tid);

    // lane addressing (row within 16-row ldmatrix group, 16B column select)
    const int a_row = wm * 32 + (lane & 15);
    const int a_kad = (lane >> 4) * 16;
    const int b_row = wn * 32 + ((lane >> 4) << 3) + (lane & 7);
    const int b_kad = ((lane >> 3) & 1) * 16;

    for (int t = 0; t < NC; t++) {
        if (t == NC - 1) asm volatile("cp.async.wait_group 0;" ::: "memory");
        else             asm volatile("cp.async.wait_group 1;" ::: "memory");
        __syncthreads();

        if (t + 2 < NC)
            load_stage(ar, Bg, sA[(t + 2) % 3], sB[(t + 2) % 3], t + 2, tid);

        const uint32_t cA = sA[t % 3];
        const uint32_t cB = sB[t % 3];
#pragma unroll
        for (int ks = 0; ks < 4; ks++) {
            const uint32_t kboff = ks * 32;  // 16 halfs = 32 B
            uint32_t a[2][4];
#pragma unroll
            for (int mi = 0; mi < 2; mi++) {
                uint32_t full = cA + swz((uint32_t)((a_row + mi * 16) * 128 + kboff + a_kad));
                asm volatile("ldmatrix.sync.aligned.m8n8.x4.shared.b16 {%0,%1,%2,%3}, [%4];"
                             : "=r"(a[mi][0]), "=r"(a[mi][1]), "=r"(a[mi][2]), "=r"(a[mi][3])
                             : "r"(full));
            }
            uint32_t bf[2][4];
#pragma unroll
            for (int nb = 0; nb < 2; nb++) {
                uint32_t full = cB + swz((uint32_t)((b_row + nb * 16) * 128 + kboff + b_kad));
                asm volatile("ldmatrix.sync.aligned.m8n8.x4.shared.b16 {%0,%1,%2,%3}, [%4];"
                             : "=r"(bf[nb][0]), "=r"(bf[nb][1]), "=r"(bf[nb][2]), "=r"(bf[nb][3])
                             : "r"(full));
            }
#pragma unroll
            for (int mi = 0; mi < 2; mi++)
#pragma unroll
                for (int ni = 0; ni < 4; ni++) {
                    const int nb = ni >> 1, hp = (ni & 1) * 2;
                    asm volatile(
                        "mma.sync.aligned.m16n8k16.row.col.f32.f16.f16.f32 "
                        "{%0,%1,%2,%3}, {%4,%5,%6,%7}, {%8,%9}, {%0,%1,%2,%3};"
                        : "+f"(acc[mi][ni][0]), "+f"(acc[mi][ni][1]),
                          "+f"(acc[mi][ni][2]), "+f"(acc[mi][ni][3])
                        : "r"(a[mi][0]), "r"(a[mi][1]), "r"(a[mi][2]), "r"(a[mi][3]),
                          "r"(bf[nb][hp]), "r"(bf[nb][hp + 1]));
                }
        }
        // no bottom barrier: top barrier of t+1 protects stage reuse
    }

    // ---- Epilogue: smem transpose -> coalesced stores ----
    __syncthreads();
    float* obuf = (float*)dsm;             // [128 i][132 m]
#pragma unroll
    for (int mi = 0; mi < 2; mi++) {
#pragma unroll
        for (int ni = 0; ni < 4; ni++) {
            int ml = wm * 32 + mi * 16 + (lane >> 2);
            int il = wn * 32 + ni * 8 + (lane & 3) * 2;
            obuf[il * 132 + ml]            = acc[mi][ni][0];
            obuf[(il + 1) * 132 + ml]      = acc[mi][ni][1];
            obuf[il * 132 + ml + 8]        = acc[mi][ni][2];
            obuf[(il + 1) * 132 + ml + 8]  = acc[mi][ni][3];
        }
    }
    __syncthreads();

    const int i_base = bn * 128;
    const int m_base = bm * 128;
    for (int idx = tid; idx < 128 * 128; idx += 512) {
        int il = idx >> 7, ml = idx & 127;
        int m  = m_base + ml;
        int b  = m / 49;
        int np = m - b * 49;
        out[(size_t)(b * NDIM + i_base + il) * 49 + np] = obuf[il * 132 + ml];
    }
}

// ---------------------------------------------------------------------------
extern "C" void kernel_launch(void* const* d_in, const int* in_sizes, int n_in,
                              void* d_out, int out_size) {
    const float* x = (const float*)d_in[0];   // (1024, 512, 7, 7)
    const float* W = (const float*)d_in[1];   // (256, 3, 3, 512)
    float* out = (float*)d_out;               // (1024, 512, 7, 7)

    cudaFuncSetAttribute(prep, cudaFuncAttributeMaxDynamicSharedMemorySize,
                         HW * XP2 * (int)sizeof(float));
    cudaFuncSetAttribute(gemm_f16, cudaFuncAttributeMaxDynamicSharedMemorySize, DSMEM);

    prep<<<2 * BATCH + 288, 512, HW * XP2 * sizeof(float)>>>(x, W);
    gemm_f16<<<dim3(NDIM / 128, MDIM / 128), 512, DSMEM>>>(out);
}

// round 13
// speedup vs baseline: 1.2644x; 1.2644x over previous
#include <cuda_runtime.h>
#include <cuda_fp16.h>
#include <cstdint>

#define BATCH 1024
#define CIN   512
#define HW    49
#define KDIM  2304          // 9 * 256
#define MDIM  50176         // 1024 * 49
#define NDIM  512

// Scratch (module-load allocation; legal per harness rules)
// G[b][j][n][w][l]: folded two-group shifted sum; l innermost (256 halfs = 512B rows)
__device__ __align__(16) __half G_g[(size_t)BATCH * 3 * HW * 256];   // 77 MB
__device__ __align__(16) __half Whn_g[(size_t)NDIM * KDIM];          // [i][kk] K-major

// ---------------------------------------------------------------------------
// helpers
// ---------------------------------------------------------------------------
__device__ __forceinline__ uint32_t s2u(const void* p) {
    uint32_t a;
    asm("{ .reg .u64 t; cvta.to.shared.u64 t, %1; cvt.u32.u64 %0, t; }" : "=r"(a) : "l"(p));
    return a;
}
__device__ __forceinline__ uint32_t swz(uint32_t o) { return o ^ ((o >> 3) & 0x70); }

// ---------------------------------------------------------------------------
// Phase 1 (merged): blocks [0, 2048) build G; blocks [2048, 2336) transpose W.
// (unchanged from R9 — proven)
// ---------------------------------------------------------------------------
#define XP2 260
#define GWORK (3 * HW * 16)   // 2352 items per prep_g block

__global__ __launch_bounds__(512, 2) void prep(const float* __restrict__ x,
                                               const float* __restrict__ W) {
    extern __shared__ float sm[];

    if (blockIdx.x < 2 * BATCH) {
        const int b    = blockIdx.x >> 1;
        const int half = blockIdx.x & 1;
        const float* xb = x + (size_t)b * CIN * HW;

        for (int i = threadIdx.x; i < 256 * HW; i += blockDim.x) {
            int cc = i / HW;
            int hw = i - cc * HW;
            int c  = (cc < 128) ? (half * 128 + cc) : (128 + half * 128 + cc);
            sm[hw * XP2 + cc] = xb[c * HW + hw];
        }
        __syncthreads();

        uint4* gout = (uint4*)(G_g + (size_t)b * 3 * HW * 256);

        for (int base = threadIdx.x; base < GWORK; base += 1024) {
            int idx0 = base;
            int idx1 = base + 512;
            const bool has1 = (idx1 < GWORK);

            int l8_0 = idx0 & 15,  rr0 = idx0 >> 4;
            int l8_1 = idx1 & 15,  rr1 = idx1 >> 4;

            int j0 = rr0 / 49, nw0 = rr0 - j0 * 49, n0 = nw0 / 7, w0 = nw0 - 7 * n0;
            int j1 = rr1 / 49, nw1 = rr1 - j1 * 49, n1 = nw1 / 7, w1 = nw1 - 7 * n1;

            int hb0 = n0 + j0 - 1, ha0 = ((n0 + 6) % 7) + j0 - 1;
            int hb1 = n1 + j1 - 1, ha1 = ((n1 + 6) % 7) + j1 - 1;
            bool bv0 = (hb0 >= 0) && (hb0 < 7), av0 = (ha0 >= 0) && (ha0 < 7);
            bool bv1 = has1 && (hb1 >= 0) && (hb1 < 7);
            bool av1 = has1 && (ha1 >= 0) && (ha1 < 7);

            const float4* pa0 = (const float4*)(sm + (ha0 * 7 + w0) * XP2 + 128 + l8_0 * 8);
            const float4* pb0 = (const float4*)(sm + (hb0 * 7 + w0) * XP2 + l8_0 * 8);
            const float4* pa1 = (const float4*)(sm + (ha1 * 7 + w1) * XP2 + 128 + l8_1 * 8);
            const float4* pb1 = (const float4*)(sm + (hb1 * 7 + w1) * XP2 + l8_1 * 8);

            float4 a00 = {0,0,0,0}, a01 = {0,0,0,0}, b00 = {0,0,0,0}, b01 = {0,0,0,0};
            float4 a10 = {0,0,0,0}, a11 = {0,0,0,0}, b10 = {0,0,0,0}, b11 = {0,0,0,0};
            if (av0) { a00 = pa0[0]; a01 = pa0[1]; }
            if (bv0) { b00 = pb0[0]; b01 = pb0[1]; }
            if (av1) { a10 = pa1[0]; a11 = pa1[1]; }
            if (bv1) { b10 = pb1[0]; b11 = pb1[1]; }

            {
                __half2 p0 = __floats2half2_rn(a00.x + b00.x, a00.y + b00.y);
                __half2 p1 = __floats2half2_rn(a00.z + b00.z, a00.w + b00.w);
                __half2 p2 = __floats2half2_rn(a01.x + b01.x, a01.y + b01.y);
                __half2 p3 = __floats2half2_rn(a01.z + b01.z, a01.w + b01.w);
                uint4 o;
                o.x = *reinterpret_cast<uint32_t*>(&p0);
                o.y = *reinterpret_cast<uint32_t*>(&p1);
                o.z = *reinterpret_cast<uint32_t*>(&p2);
                o.w = *reinterpret_cast<uint32_t*>(&p3);
                gout[rr0 * 32 + half * 16 + l8_0] = o;
            }
            if (has1) {
                __half2 p0 = __floats2half2_rn(a10.x + b10.x, a10.y + b10.y);
                __half2 p1 = __floats2half2_rn(a10.z + b10.z, a10.w + b10.w);
                __half2 p2 = __floats2half2_rn(a11.x + b11.x, a11.y + b11.y);
                __half2 p3 = __floats2half2_rn(a11.z + b11.z, a11.w + b11.w);
                uint4 o;
                o.x = *reinterpret_cast<uint32_t*>(&p0);
                o.y = *reinterpret_cast<uint32_t*>(&p1);
                o.z = *reinterpret_cast<uint32_t*>(&p2);
                o.w = *reinterpret_cast<uint32_t*>(&p3);
                gout[rr1 * 32 + half * 16 + l8_1] = o;
            }
        }
    } else {
        float* tile = sm;                       // [64][65]
        const int bid2 = blockIdx.x - 2 * BATCH;   // 0..287
        const int jk = bid2 / 32;
        const int r  = bid2 - jk * 32;
        const int lt = r >> 3;
        const int it = r & 7;

        for (int i = threadIdx.x; i < 64 * 64; i += blockDim.x) {
            int ll = i >> 6, ii = i & 63;
            tile[ll * 65 + ii] = W[((size_t)(lt * 64 + ll) * 9 + jk) * NDIM + it * 64 + ii];
        }
        __syncthreads();

        __half2* out2 = (__half2*)Whn_g;
        for (int i = threadIdx.x; i < 64 * 32; i += blockDim.x) {
            int ii = i >> 5, l2 = i & 31;
            float v0 = tile[(l2 * 2) * 65 + ii];
            float v1 = tile[(l2 * 2 + 1) * 65 + ii];
            out2[(size_t)(it * 64 + ii) * (KDIM / 2) + jk * 128 + lt * 32 + l2] =
                __floats2half2_rn(v0, v1);
        }
    }
}

// ---------------------------------------------------------------------------
// Phase 2: fused-im2col GEMM  out[m][i] = sum_k A[m][k] * Whn[i][k]
// R9 mainloop (256 thr, 8 warps, warp 64x32, 3-stage) with ONE change:
// B fragments via ldmatrix.x4 (16 rows x 16 halfs) instead of x2 — halves
// B-LDSM instruction count, relieving the smem-crossbar bottleneck.
// ---------------------------------------------------------------------------
#define BK 64
#define NC (KDIM / BK)        // 36
#define STG_H 8192            // halfs per stage per operand (128 * 64)
#define DSMEM (3 * 2 * STG_H * 2 + 256)

struct ARow {
    const __half* g[4];   // per q: G base for this row (b,n and c*8 folded in)
    int p[4];
};

__device__ __forceinline__ void load_stage(
    const ARow& ar, const __half* __restrict__ Bg,
    uint32_t sA, uint32_t sB, int chunk, int tid)
{
    const int jk = chunk >> 2;
    const int l0 = (chunk & 3) << 6;
    const int j  = (jk * 11) >> 5;        // jk/3 for jk in [0,8]
    const int k  = jk - 3 * j;
    const int off0 = j * (49 * 256) + l0;
    const int r0 = tid >> 3;
    const int c16 = (tid & 7) * 16;
#pragma unroll
    for (int q = 0; q < 4; q++) {         // A: 128 rows x 8 chunks of 16B
        const int p = ar.p[q];
        int w2 = p + k + 5; if (w2 >= 7) w2 -= 7;
        const uint32_t vsz = ((unsigned)(p + k - 1) <= 6u) ? 16u : 0u;
        const uint32_t dst = sA + swz((uint32_t)((r0 + q * 32) * 128 + c16));
        const __half* src = ar.g[q] + off0 + w2 * 256;
        asm volatile("cp.async.cg.shared.global [%0], [%1], 16, %2;"
                     :: "r"(dst), "l"(src), "r"(vsz));
    }
    const int k0 = chunk * BK;
#pragma unroll
    for (int q = 0; q < 4; q++) {         // B: 1024 x 16B
        int id = tid + q * 256;
        int r = id >> 3, c = id & 7;
        asm volatile("cp.async.cg.shared.global [%0], [%1], 16;"
                     :: "r"(sB + swz((uint32_t)(r * 128 + c * 16))),
                        "l"(Bg + (size_t)r * KDIM + k0 + c * 8));
    }
    asm volatile("cp.async.commit_group;" ::: "memory");
}

__global__ __launch_bounds__(256, 2) void gemm_f16(float* __restrict__ out) {
    extern __shared__ char dsm[];
    const uint32_t sbase = (s2u(dsm) + 127) & ~127u;

    const int bn   = blockIdx.x;     // 0..3
    const int bm   = blockIdx.y;     // 0..391
    const int tid  = threadIdx.x;
    const int wid  = tid >> 5;
    const int lane = tid & 31;
    const int wm   = wid >> 2;       // 0..1
    const int wn   = wid & 3;        // 0..3

    const __half* Bg = Whn_g + (size_t)bn * 128 * KDIM;

    ARow ar;
    {
        const int r0 = tid >> 3;
        const int c8 = (tid & 7) * 8;
#pragma unroll
        for (int q = 0; q < 4; q++) {
            int m  = bm * 128 + r0 + q * 32;
            int b  = m / 49;
            int np = m - b * 49;
            int n  = np / 7;
            ar.p[q] = np - 7 * n;
            ar.g[q] = G_g + ((size_t)b * 147 + n * 7) * 256 + c8;
        }
    }

    uint32_t sA[3], sB[3];
#pragma unroll
    for (int s = 0; s < 3; s++) {
        sA[s] = sbase + s * (STG_H * 2);
        sB[s] = sbase + (3 + s) * (STG_H * 2);
    }

    float acc[4][4][4];
#pragma unroll
    for (int a = 0; a < 4; a++)
#pragma unroll
        for (int b = 0; b < 4; b++)
#pragma unroll
            for (int c = 0; c < 4; c++) acc[a][b][c] = 0.f;

    load_stage(ar, Bg, sA[0], sB[0], 0, tid);
    load_stage(ar, Bg, sA[1], sB[1], 1, tid);

    // lane addressing
    const int a_row = wm * 64 + (lane & 15);
    const int a_kad = (lane >> 4) * 16;
    const int b_row = wn * 32 + ((lane >> 4) << 3) + (lane & 7);
    const int b_kad = ((lane >> 3) & 1) * 16;

    for (int t = 0; t < NC; t++) {
        if (t == NC - 1) asm volatile("cp.async.wait_group 0;" ::: "memory");
        else             asm volatile("cp.async.wait_group 1;" ::: "memory");
        __syncthreads();

        if (t + 2 < NC)
            load_stage(ar, Bg, sA[(t + 2) % 3], sB[(t + 2) % 3], t + 2, tid);

        const uint32_t cA = sA[t % 3];
        const uint32_t cB = sB[t % 3];
#pragma unroll
        for (int ks = 0; ks < 4; ks++) {
            const uint32_t kboff = ks * 32;  // 16 halfs = 32 B
            uint32_t a[4][4];
#pragma unroll
            for (int mi = 0; mi < 4; mi++) {
                uint32_t full = cA + swz((uint32_t)((a_row + mi * 16) * 128 + kboff + a_kad));
                asm volatile("ldmatrix.sync.aligned.m8n8.x4.shared.b16 {%0,%1,%2,%3}, [%4];"
                             : "=r"(a[mi][0]), "=r"(a[mi][1]), "=r"(a[mi][2]), "=r"(a[mi][3])
                             : "r"(full));
            }
            uint32_t bf[2][4];
#pragma unroll
            for (int nb = 0; nb < 2; nb++) {
                uint32_t full = cB + swz((uint32_t)((b_row + nb * 16) * 128 + kboff + b_kad));
                asm volatile("ldmatrix.sync.aligned.m8n8.x4.shared.b16 {%0,%1,%2,%3}, [%4];"
                             : "=r"(bf[nb][0]), "=r"(bf[nb][1]), "=r"(bf[nb][2]), "=r"(bf[nb][3])
                             : "r"(full));
            }
#pragma unroll
            for (int mi = 0; mi < 4; mi++)
#pragma unroll
                for (int ni = 0; ni < 4; ni++) {
                    const int nb = ni >> 1, hp = (ni & 1) * 2;
                    asm volatile(
                        "mma.sync.aligned.m16n8k16.row.col.f32.f16.f16.f32 "
                        "{%0,%1,%2,%3}, {%4,%5,%6,%7}, {%8,%9}, {%0,%1,%2,%3};"
                        : "+f"(acc[mi][ni][0]), "+f"(acc[mi][ni][1]),
                          "+f"(acc[mi][ni][2]), "+f"(acc[mi][ni][3])
                        : "r"(a[mi][0]), "r"(a[mi][1]), "r"(a[mi][2]), "r"(a[mi][3]),
                          "r"(bf[nb][hp]), "r"(bf[nb][hp + 1]));
                }
        }
        // no bottom barrier: top barrier of t+1 protects stage reuse
    }

    // ---- Epilogue: smem transpose -> coalesced stores ----
    __syncthreads();
    float* obuf = (float*)dsm;             // [128 i][132 m]
#pragma unroll
    for (int mi = 0; mi < 4; mi++) {
#pragma unroll
        for (int ni = 0; ni < 4; ni++) {
            int ml = wm * 64 + mi * 16 + (lane >> 2);
            int il = wn * 32 + ni * 8 + (lane & 3) * 2;
            obuf[il * 132 + ml]            = acc[mi][ni][0];
            obuf[(il + 1) * 132 + ml]      = acc[mi][ni][1];
            obuf[il * 132 + ml + 8]        = acc[mi][ni][2];
            obuf[(il + 1) * 132 + ml + 8]  = acc[mi][ni][3];
        }
    }
    __syncthreads();

    const int i_base = bn * 128;
    const int m_base = bm * 128;
    for (int idx = tid; idx < 128 * 128; idx += 256) {
        int il = idx >> 7, ml = idx & 127;
        int m  = m_base + ml;
        int b  = m / 49;
        int np = m - b * 49;
        out[(size_t)(b * NDIM + i_base + il) * 49 + np] = obuf[il * 132 + ml];
    }
}

// ---------------------------------------------------------------------------
extern "C" void kernel_launch(void* const* d_in, const int* in_sizes, int n_in,
                              void* d_out, int out_size) {
    const float* x = (const float*)d_in[0];   // (1024, 512, 7, 7)
    const float* W = (const float*)d_in[1];   // (256, 3, 3, 512)
    float* out = (float*)d_out;               // (1024, 512, 7, 7)

    cudaFuncSetAttribute(prep, cudaFuncAttributeMaxDynamicSharedMemorySize,
                         HW * XP2 * (int)sizeof(float));
    cudaFuncSetAttribute(gemm_f16, cudaFuncAttributeMaxDynamicSharedMemorySize, DSMEM);

    prep<<<2 * BATCH + 288, 512, HW * XP2 * sizeof(float)>>>(x, W);
    gemm_f16<<<dim3(NDIM / 128, MDIM / 128), 256, DSMEM>>>(out);
}

// round 14
// speedup vs baseline: 1.2727x; 1.0065x over previous
#include <cuda_runtime.h>
#include <cuda_fp16.h>
#include <cstdint>

#define BATCH 1024
#define CIN   512
#define HW    49
#define KDIM  2304          // 9 * 256
#define MDIM  50176         // 1024 * 49
#define NDIM  512

// Scratch (module-load allocation; legal per harness rules)
// G[b][j][n][w][l]: folded two-group shifted sum; l innermost (256 halfs = 512B rows)
__device__ __align__(16) __half G_g[(size_t)BATCH * 3 * HW * 256];   // 77 MB
__device__ __align__(16) __half Whn_g[(size_t)NDIM * KDIM];          // [i][kk] K-major

// ---------------------------------------------------------------------------
// helpers
// ---------------------------------------------------------------------------
__device__ __forceinline__ uint32_t s2u(const void* p) {
    uint32_t a;
    asm("{ .reg .u64 t; cvta.to.shared.u64 t, %1; cvt.u32.u64 %0, t; }" : "=r"(a) : "l"(p));
    return a;
}
__device__ __forceinline__ uint32_t swz(uint32_t o) { return o ^ ((o >> 3) & 0x70); }

// ---------------------------------------------------------------------------
// Phase 1 (merged): blocks [0, 2048) build G; blocks [2048, 2336) transpose W.
// (unchanged — proven)
// ---------------------------------------------------------------------------
#define XP2 260
#define GWORK (3 * HW * 16)   // 2352 items per prep_g block

__global__ __launch_bounds__(512, 2) void prep(const float* __restrict__ x,
                                               const float* __restrict__ W) {
    extern __shared__ float sm[];

    if (blockIdx.x < 2 * BATCH) {
        const int b    = blockIdx.x >> 1;
        const int half = blockIdx.x & 1;
        const float* xb = x + (size_t)b * CIN * HW;

        for (int i = threadIdx.x; i < 256 * HW; i += blockDim.x) {
            int cc = i / HW;
            int hw = i - cc * HW;
            int c  = (cc < 128) ? (half * 128 + cc) : (128 + half * 128 + cc);
            sm[hw * XP2 + cc] = xb[c * HW + hw];
        }
        __syncthreads();

        uint4* gout = (uint4*)(G_g + (size_t)b * 3 * HW * 256);

        for (int base = threadIdx.x; base < GWORK; base += 1024) {
            int idx0 = base;
            int idx1 = base + 512;
            const bool has1 = (idx1 < GWORK);

            int l8_0 = idx0 & 15,  rr0 = idx0 >> 4;
            int l8_1 = idx1 & 15,  rr1 = idx1 >> 4;

            int j0 = rr0 / 49, nw0 = rr0 - j0 * 49, n0 = nw0 / 7, w0 = nw0 - 7 * n0;
            int j1 = rr1 / 49, nw1 = rr1 - j1 * 49, n1 = nw1 / 7, w1 = nw1 - 7 * n1;

            int hb0 = n0 + j0 - 1, ha0 = ((n0 + 6) % 7) + j0 - 1;
            int hb1 = n1 + j1 - 1, ha1 = ((n1 + 6) % 7) + j1 - 1;
            bool bv0 = (hb0 >= 0) && (hb0 < 7), av0 = (ha0 >= 0) && (ha0 < 7);
            bool bv1 = has1 && (hb1 >= 0) && (hb1 < 7);
            bool av1 = has1 && (ha1 >= 0) && (ha1 < 7);

            const float4* pa0 = (const float4*)(sm + (ha0 * 7 + w0) * XP2 + 128 + l8_0 * 8);
            const float4* pb0 = (const float4*)(sm + (hb0 * 7 + w0) * XP2 + l8_0 * 8);
            const float4* pa1 = (const float4*)(sm + (ha1 * 7 + w1) * XP2 + 128 + l8_1 * 8);
            const float4* pb1 = (const float4*)(sm + (hb1 * 7 + w1) * XP2 + l8_1 * 8);

            float4 a00 = {0,0,0,0}, a01 = {0,0,0,0}, b00 = {0,0,0,0}, b01 = {0,0,0,0};
            float4 a10 = {0,0,0,0}, a11 = {0,0,0,0}, b10 = {0,0,0,0}, b11 = {0,0,0,0};
            if (av0) { a00 = pa0[0]; a01 = pa0[1]; }
            if (bv0) { b00 = pb0[0]; b01 = pb0[1]; }
            if (av1) { a10 = pa1[0]; a11 = pa1[1]; }
            if (bv1) { b10 = pb1[0]; b11 = pb1[1]; }

            {
                __half2 p0 = __floats2half2_rn(a00.x + b00.x, a00.y + b00.y);
                __half2 p1 = __floats2half2_rn(a00.z + b00.z, a00.w + b00.w);
                __half2 p2 = __floats2half2_rn(a01.x + b01.x, a01.y + b01.y);
                __half2 p3 = __floats2half2_rn(a01.z + b01.z, a01.w + b01.w);
                uint4 o;
                o.x = *reinterpret_cast<uint32_t*>(&p0);
                o.y = *reinterpret_cast<uint32_t*>(&p1);
                o.z = *reinterpret_cast<uint32_t*>(&p2);
                o.w = *reinterpret_cast<uint32_t*>(&p3);
                gout[rr0 * 32 + half * 16 + l8_0] = o;
            }
            if (has1) {
                __half2 p0 = __floats2half2_rn(a10.x + b10.x, a10.y + b10.y);
                __half2 p1 = __floats2half2_rn(a10.z + b10.z, a10.w + b10.w);
                __half2 p2 = __floats2half2_rn(a11.x + b11.x, a11.y + b11.y);
                __half2 p3 = __floats2half2_rn(a11.z + b11.z, a11.w + b11.w);
                uint4 o;
                o.x = *reinterpret_cast<uint32_t*>(&p0);
                o.y = *reinterpret_cast<uint32_t*>(&p1);
                o.z = *reinterpret_cast<uint32_t*>(&p2);
                o.w = *reinterpret_cast<uint32_t*>(&p3);
                gout[rr1 * 32 + half * 16 + l8_1] = o;
            }
        }
    } else {
        float* tile = sm;                       // [64][65]
        const int bid2 = blockIdx.x - 2 * BATCH;   // 0..287
        const int jk = bid2 / 32;
        const int r  = bid2 - jk * 32;
        const int lt = r >> 3;
        const int it = r & 7;

        for (int i = threadIdx.x; i < 64 * 64; i += blockDim.x) {
            int ll = i >> 6, ii = i & 63;
            tile[ll * 65 + ii] = W[((size_t)(lt * 64 + ll) * 9 + jk) * NDIM + it * 64 + ii];
        }
        __syncthreads();

        __half2* out2 = (__half2*)Whn_g;
        for (int i = threadIdx.x; i < 64 * 32; i += blockDim.x) {
            int ii = i >> 5, l2 = i & 31;
            float v0 = tile[(l2 * 2) * 65 + ii];
            float v1 = tile[(l2 * 2 + 1) * 65 + ii];
            out2[(size_t)(it * 64 + ii) * (KDIM / 2) + jk * 128 + lt * 32 + l2] =
                __floats2half2_rn(v0, v1);
        }
    }
}

// ---------------------------------------------------------------------------
// Phase 2: fused-im2col GEMM  out[m][i] = sum_k A[m][k] * Whn[i][k]
// R12 structure + manual fragment double-buffering across ks: LDSM for ks+1
// issued before MMAs of ks, hiding ldmatrix latency under the tensor burst.
// ---------------------------------------------------------------------------
#define BK 64
#define NC (KDIM / BK)        // 36
#define STG_H 8192            // halfs per stage per operand (128 * 64)
#define DSMEM (3 * 2 * STG_H * 2 + 256)

struct ARow {
    const __half* g[4];   // per q: G base for this row (b,n and c*8 folded in)
    int p[4];
};

__device__ __forceinline__ void load_stage(
    const ARow& ar, const __half* __restrict__ Bg,
    uint32_t sA, uint32_t sB, int chunk, int tid)
{
    const int jk = chunk >> 2;
    const int l0 = (chunk & 3) << 6;
    const int j  = (jk * 11) >> 5;        // jk/3 for jk in [0,8]
    const int k  = jk - 3 * j;
    const int off0 = j * (49 * 256) + l0;
    const int r0 = tid >> 3;
    const int c16 = (tid & 7) * 16;
#pragma unroll
    for (int q = 0; q < 4; q++) {         // A: 128 rows x 8 chunks of 16B
        const int p = ar.p[q];
        int w2 = p + k + 5; if (w2 >= 7) w2 -= 7;
        const uint32_t vsz = ((unsigned)(p + k - 1) <= 6u) ? 16u : 0u;
        const uint32_t dst = sA + swz((uint32_t)((r0 + q * 32) * 128 + c16));
        const __half* src = ar.g[q] + off0 + w2 * 256;
        asm volatile("cp.async.cg.shared.global [%0], [%1], 16, %2;"
                     :: "r"(dst), "l"(src), "r"(vsz));
    }
    const int k0 = chunk * BK;
#pragma unroll
    for (int q = 0; q < 4; q++) {         // B: 1024 x 16B
        int id = tid + q * 256;
        int r = id >> 3, c = id & 7;
        asm volatile("cp.async.cg.shared.global [%0], [%1], 16;"
                     :: "r"(sB + swz((uint32_t)(r * 128 + c * 16))),
                        "l"(Bg + (size_t)r * KDIM + k0 + c * 8));
    }
    asm volatile("cp.async.commit_group;" ::: "memory");
}

// Load A(4 x ldmatrix.x4) + B(2 x ldmatrix.x4) fragments for kstep ks into slot s.
#define LOADFRAG(ks, s) do {                                                        \
    const uint32_t _kb = (uint32_t)((ks) * 32);                                     \
    _Pragma("unroll")                                                               \
    for (int _mi = 0; _mi < 4; _mi++) {                                             \
        uint32_t _fa = cA + swz((uint32_t)((a_row + _mi * 16) * 128 + _kb + a_kad));\
        asm volatile("ldmatrix.sync.aligned.m8n8.x4.shared.b16 {%0,%1,%2,%3}, [%4];"\
                     : "=r"(afr[s][_mi][0]), "=r"(afr[s][_mi][1]),                  \
                       "=r"(afr[s][_mi][2]), "=r"(afr[s][_mi][3])                   \
                     : "r"(_fa));                                                   \
    }                                                                               \
    _Pragma("unroll")                                                               \
    for (int _nb = 0; _nb < 2; _nb++) {                                             \
        uint32_t _fb = cB + swz((uint32_t)((b_row + _nb * 16) * 128 + _kb + b_kad));\
        asm volatile("ldmatrix.sync.aligned.m8n8.x4.shared.b16 {%0,%1,%2,%3}, [%4];"\
                     : "=r"(bfr[s][_nb][0]), "=r"(bfr[s][_nb][1]),                  \
                       "=r"(bfr[s][_nb][2]), "=r"(bfr[s][_nb][3])                   \
                     : "r"(_fb));                                                   \
    }                                                                               \
} while (0)

__global__ __launch_bounds__(256, 2) void gemm_f16(float* __restrict__ out) {
    extern __shared__ char dsm[];
    const uint32_t sbase = (s2u(dsm) + 127) & ~127u;

    const int bn   = blockIdx.x;     // 0..3
    const int bm   = blockIdx.y;     // 0..391
    const int tid  = threadIdx.x;
    const int wid  = tid >> 5;
    const int lane = tid & 31;
    const int wm   = wid >> 2;       // 0..1
    const int wn   = wid & 3;        // 0..3

    const __half* Bg = Whn_g + (size_t)bn * 128 * KDIM;

    ARow ar;
    {
        const int r0 = tid >> 3;
        const int c8 = (tid & 7) * 8;
#pragma unroll
        for (int q = 0; q < 4; q++) {
            int m  = bm * 128 + r0 + q * 32;
            int b  = m / 49;
            int np = m - b * 49;
            int n  = np / 7;
            ar.p[q] = np - 7 * n;
            ar.g[q] = G_g + ((size_t)b * 147 + n * 7) * 256 + c8;
        }
    }

    uint32_t sA[3], sB[3];
#pragma unroll
    for (int s = 0; s < 3; s++) {
        sA[s] = sbase + s * (STG_H * 2);
        sB[s] = sbase + (3 + s) * (STG_H * 2);
    }

    float acc[4][4][4];
#pragma unroll
    for (int a = 0; a < 4; a++)
#pragma unroll
        for (int b = 0; b < 4; b++)
#pragma unroll
            for (int c = 0; c < 4; c++) acc[a][b][c] = 0.f;

    load_stage(ar, Bg, sA[0], sB[0], 0, tid);
    load_stage(ar, Bg, sA[1], sB[1], 1, tid);

    // lane addressing
    const int a_row = wm * 64 + (lane & 15);
    const int a_kad = (lane >> 4) * 16;
    const int b_row = wn * 32 + ((lane >> 4) << 3) + (lane & 7);
    const int b_kad = ((lane >> 3) & 1) * 16;

    for (int t = 0; t < NC; t++) {
        if (t == NC - 1) asm volatile("cp.async.wait_group 0;" ::: "memory");
        else             asm volatile("cp.async.wait_group 1;" ::: "memory");
        __syncthreads();

        if (t + 2 < NC)
            load_stage(ar, Bg, sA[(t + 2) % 3], sB[(t + 2) % 3], t + 2, tid);

        const uint32_t cA = sA[t % 3];
        const uint32_t cB = sB[t % 3];

        uint32_t afr[2][4][4];
        uint32_t bfr[2][2][4];
        LOADFRAG(0, 0);

#pragma unroll
        for (int ks = 0; ks < 4; ks++) {
            const int cur = ks & 1;
            if (ks < 3) {
                const int nxt = cur ^ 1;
                if (nxt) LOADFRAG(ks + 1, 1); else LOADFRAG(ks + 1, 0);
            }
#pragma unroll
            for (int mi = 0; mi < 4; mi++)
#pragma unroll
                for (int ni = 0; ni < 4; ni++) {
                    const int nb = ni >> 1, hp = (ni & 1) * 2;
                    asm volatile(
                        "mma.sync.aligned.m16n8k16.row.col.f32.f16.f16.f32 "
                        "{%0,%1,%2,%3}, {%4,%5,%6,%7}, {%8,%9}, {%0,%1,%2,%3};"
                        : "+f"(acc[mi][ni][0]), "+f"(acc[mi][ni][1]),
                          "+f"(acc[mi][ni][2]), "+f"(acc[mi][ni][3])
                        : "r"(afr[cur][mi][0]), "r"(afr[cur][mi][1]),
                          "r"(afr[cur][mi][2]), "r"(afr[cur][mi][3]),
                          "r"(bfr[cur][nb][hp]), "r"(bfr[cur][nb][hp + 1]));
                }
        }
        // no bottom barrier: top barrier of t+1 protects stage reuse
    }

    // ---- Epilogue: smem transpose -> coalesced stores ----
    __syncthreads();
    float* obuf = (float*)dsm;             // [128 i][132 m]
#pragma unroll
    for (int mi = 0; mi < 4; mi++) {
#pragma unroll
        for (int ni = 0; ni < 4; ni++) {
            int ml = wm * 64 + mi * 16 + (lane >> 2);
            int il = wn * 32 + ni * 8 + (lane & 3) * 2;
            obuf[il * 132 + ml]            = acc[mi][ni][0];
            obuf[(il + 1) * 132 + ml]      = acc[mi][ni][1];
            obuf[il * 132 + ml + 8]        = acc[mi][ni][2];
            obuf[(il + 1) * 132 + ml + 8]  = acc[mi][ni][3];
        }
    }
    __syncthreads();

    const int i_base = bn * 128;
    const int m_base = bm * 128;
    for (int idx = tid; idx < 128 * 128; idx += 256) {
        int il = idx >> 7, ml = idx & 127;
        int m  = m_base + ml;
        int b  = m / 49;
        int np = m - b * 49;
        out[(size_t)(b * NDIM + i_base + il) * 49 + np] = obuf[il * 132 + ml];
    }
}

// ---------------------------------------------------------------------------
extern "C" void kernel_launch(void* const* d_in, const int* in_sizes, int n_in,
                              void* d_out, int out_size) {
    const float* x = (const float*)d_in[0];   // (1024, 512, 7, 7)
    const float* W = (const float*)d_in[1];   // (256, 3, 3, 512)
    float* out = (float*)d_out;               // (1024, 512, 7, 7)

    cudaFuncSetAttribute(prep, cudaFuncAttributeMaxDynamicSharedMemorySize,
                         HW * XP2 * (int)sizeof(float));
    cudaFuncSetAttribute(gemm_f16, cudaFuncAttributeMaxDynamicSharedMemorySize, DSMEM);

    prep<<<2 * BATCH + 288, 512, HW * XP2 * sizeof(float)>>>(x, W);
    gemm_f16<<<dim3(NDIM / 128, MDIM / 128), 256, DSMEM>>>(out);
}

// round 15
// speedup vs baseline: 1.3987x; 1.0990x over previous
#include <cuda_runtime.h>
#include <cuda_fp16.h>
#include <cstdint>

#define BATCH 1024
#define CIN   512
#define HW    49
#define KDIM  2304          // 9 * 256
#define MDIM  50176         // 1024 * 49
#define NDIM  512

__device__ __align__(16) __half G_g[(size_t)BATCH * 3 * HW * 256];   // 77 MB
__device__ __align__(16) __half Whn_g[(size_t)NDIM * KDIM];          // [i][kk] K-major

// ---------------------------------------------------------------------------
__device__ __forceinline__ uint32_t s2u(const void* p) {
    uint32_t a;
    asm("{ .reg .u64 t; cvta.to.shared.u64 t, %1; cvt.u32.u64 %0, t; }" : "=r"(a) : "l"(p));
    return a;
}
__device__ __forceinline__ uint32_t swz(uint32_t o) { return o ^ ((o >> 3) & 0x70); }

#define MBWAIT(addr, par) do {                                                 \
    asm volatile("{\n\t.reg .pred P1;\n\t"                                     \
        "WL%=:\n\t"                                                            \
        "mbarrier.try_wait.parity.acquire.cta.shared::cta.b64 P1, [%0], %1, 0x989680;\n\t" \
        "@P1 bra.uni WD%=;\n\t"                                                \
        "bra.uni WL%=;\n\t"                                                    \
        "WD%=:\n\t}"                                                           \
        :: "r"(addr), "r"((uint32_t)(par)) : "memory");                        \
} while (0)

// ---------------------------------------------------------------------------
// Phase 1 (merged): blocks [0, 2048) build G; blocks [2048, 2336) transpose W.
// (unchanged — proven)
// ---------------------------------------------------------------------------
#define XP2 260
#define GWORK (3 * HW * 16)

__global__ __launch_bounds__(512, 2) void prep(const float* __restrict__ x,
                                               const float* __restrict__ W) {
    extern __shared__ float sm[];

    if (blockIdx.x < 2 * BATCH) {
        const int b    = blockIdx.x >> 1;
        const int half = blockIdx.x & 1;
        const float* xb = x + (size_t)b * CIN * HW;

        for (int i = threadIdx.x; i < 256 * HW; i += blockDim.x) {
            int cc = i / HW;
            int hw = i - cc * HW;
            int c  = (cc < 128) ? (half * 128 + cc) : (128 + half * 128 + cc);
            sm[hw * XP2 + cc] = xb[c * HW + hw];
        }
        __syncthreads();

        uint4* gout = (uint4*)(G_g + (size_t)b * 3 * HW * 256);

        for (int base = threadIdx.x; base < GWORK; base += 1024) {
            int idx0 = base;
            int idx1 = base + 512;
            const bool has1 = (idx1 < GWORK);

            int l8_0 = idx0 & 15,  rr0 = idx0 >> 4;
            int l8_1 = idx1 & 15,  rr1 = idx1 >> 4;

            int j0 = rr0 / 49, nw0 = rr0 - j0 * 49, n0 = nw0 / 7, w0 = nw0 - 7 * n0;
            int j1 = rr1 / 49, nw1 = rr1 - j1 * 49, n1 = nw1 / 7, w1 = nw1 - 7 * n1;

            int hb0 = n0 + j0 - 1, ha0 = ((n0 + 6) % 7) + j0 - 1;
            int hb1 = n1 + j1 - 1, ha1 = ((n1 + 6) % 7) + j1 - 1;
            bool bv0 = (hb0 >= 0) && (hb0 < 7), av0 = (ha0 >= 0) && (ha0 < 7);
            bool bv1 = has1 && (hb1 >= 0) && (hb1 < 7);
            bool av1 = has1 && (ha1 >= 0) && (ha1 < 7);

            const float4* pa0 = (const float4*)(sm + (ha0 * 7 + w0) * XP2 + 128 + l8_0 * 8);
            const float4* pb0 = (const float4*)(sm + (hb0 * 7 + w0) * XP2 + l8_0 * 8);
            const float4* pa1 = (const float4*)(sm + (ha1 * 7 + w1) * XP2 + 128 + l8_1 * 8);
            const float4* pb1 = (const float4*)(sm + (hb1 * 7 + w1) * XP2 + l8_1 * 8);

            float4 a00 = {0,0,0,0}, a01 = {0,0,0,0}, b00 = {0,0,0,0}, b01 = {0,0,0,0};
            float4 a10 = {0,0,0,0}, a11 = {0,0,0,0}, b10 = {0,0,0,0}, b11 = {0,0,0,0};
            if (av0) { a00 = pa0[0]; a01 = pa0[1]; }
            if (bv0) { b00 = pb0[0]; b01 = pb0[1]; }
            if (av1) { a10 = pa1[0]; a11 = pa1[1]; }
            if (bv1) { b10 = pb1[0]; b11 = pb1[1]; }

            {
                __half2 p0 = __floats2half2_rn(a00.x + b00.x, a00.y + b00.y);
                __half2 p1 = __floats2half2_rn(a00.z + b00.z, a00.w + b00.w);
                __half2 p2 = __floats2half2_rn(a01.x + b01.x, a01.y + b01.y);
                __half2 p3 = __floats2half2_rn(a01.z + b01.z, a01.w + b01.w);
                uint4 o;
                o.x = *reinterpret_cast<uint32_t*>(&p0);
                o.y = *reinterpret_cast<uint32_t*>(&p1);
                o.z = *reinterpret_cast<uint32_t*>(&p2);
                o.w = *reinterpret_cast<uint32_t*>(&p3);
                gout[rr0 * 32 + half * 16 + l8_0] = o;
            }
            if (has1) {
                __half2 p0 = __floats2half2_rn(a10.x + b10.x, a10.y + b10.y);
                __half2 p1 = __floats2half2_rn(a10.z + b10.z, a10.w + b10.w);
                __half2 p2 = __floats2half2_rn(a11.x + b11.x, a11.y + b11.y);
                __half2 p3 = __floats2half2_rn(a11.z + b11.z, a11.w + b11.w);
                uint4 o;
                o.x = *reinterpret_cast<uint32_t*>(&p0);
                o.y = *reinterpret_cast<uint32_t*>(&p1);
                o.z = *reinterpret_cast<uint32_t*>(&p2);
                o.w = *reinterpret_cast<uint32_t*>(&p3);
                gout[rr1 * 32 + half * 16 + l8_1] = o;
            }
        }
    } else {
        float* tile = sm;                       // [64][65]
        const int bid2 = blockIdx.x - 2 * BATCH;
        const int jk = bid2 / 32;
        const int r  = bid2 - jk * 32;
        const int lt = r >> 3;
        const int it = r & 7;

        for (int i = threadIdx.x; i < 64 * 64; i += blockDim.x) {
            int ll = i >> 6, ii = i & 63;
            tile[ll * 65 + ii] = W[((size_t)(lt * 64 + ll) * 9 + jk) * NDIM + it * 64 + ii];
        }
        __syncthreads();

        __half2* out2 = (__half2*)Whn_g;
        for (int i = threadIdx.x; i < 64 * 32; i += blockDim.x) {
            int ii = i >> 5, l2 = i & 31;
            float v0 = tile[(l2 * 2) * 65 + ii];
            float v1 = tile[(l2 * 2 + 1) * 65 + ii];
            out2[(size_t)(it * 64 + ii) * (KDIM / 2) + jk * 128 + lt * 32 + l2] =
                __floats2half2_rn(v0, v1);
        }
    }
}

// ---------------------------------------------------------------------------
// Phase 2: fused-im2col GEMM, mbarrier-decoupled pipeline (no mainloop
// __syncthreads): full[s] count=256 armed via cp.async.mbarrier.arrive.noinc,
// empty[s] count=8 armed by lane0 per warp after the warp's reads. Warps
// free-run across chunk boundaries -> no convoy at chunk heads.
// ---------------------------------------------------------------------------
#define BK 64
#define NC (KDIM / BK)        // 36
#define STG_H 8192
#define DSMEM (3 * 2 * STG_H * 2 + 256)

struct ARow {
    const __half* g[4];
    int p[4];
};

// produce chunk -> stage (sA,sB), then arm full barrier
__device__ __forceinline__ void produce(
    const ARow& ar, const __half* __restrict__ Bg,
    uint32_t sA, uint32_t sB, int chunk, int tid, uint32_t mb_full)
{
    const int jk = chunk >> 2;
    const int l0 = (chunk & 3) << 6;
    const int j  = (jk * 11) >> 5;
    const int k  = jk - 3 * j;
    const int off0 = j * (49 * 256) + l0;
    const int r0 = tid >> 3;
    const int c16 = (tid & 7) * 16;
#pragma unroll
    for (int q = 0; q < 4; q++) {
        const int p = ar.p[q];
        int w2 = p + k + 5; if (w2 >= 7) w2 -= 7;
        const uint32_t vsz = ((unsigned)(p + k - 1) <= 6u) ? 16u : 0u;
        const uint32_t dst = sA + swz((uint32_t)((r0 + q * 32) * 128 + c16));
        const __half* src = ar.g[q] + off0 + w2 * 256;
        asm volatile("cp.async.cg.shared.global [%0], [%1], 16, %2;"
                     :: "r"(dst), "l"(src), "r"(vsz));
    }
    const int k0 = chunk * BK;
#pragma unroll
    for (int q = 0; q < 4; q++) {
        int id = tid + q * 256;
        int r = id >> 3, c = id & 7;
        asm volatile("cp.async.cg.shared.global [%0], [%1], 16;"
                     :: "r"(sB + swz((uint32_t)(r * 128 + c * 16))),
                        "l"(Bg + (size_t)r * KDIM + k0 + c * 8));
    }
    asm volatile("cp.async.mbarrier.arrive.noinc.shared.b64 [%0];"
                 :: "r"(mb_full) : "memory");
}

__global__ __launch_bounds__(256, 2) void gemm_f16(float* __restrict__ out) {
    extern __shared__ char dsm[];
    __shared__ __align__(8) uint64_t mbar[6];   // full[0..2], empty[0..2]
    const uint32_t sbase = (s2u(dsm) + 127) & ~127u;

    const int bn   = blockIdx.x;
    const int bm   = blockIdx.y;
    const int tid  = threadIdx.x;
    const int wid  = tid >> 5;
    const int lane = tid & 31;
    const int wm   = wid >> 2;
    const int wn   = wid & 3;

    const __half* Bg = Whn_g + (size_t)bn * 128 * KDIM;

    ARow ar;
    {
        const int r0 = tid >> 3;
        const int c8 = (tid & 7) * 8;
#pragma unroll
        for (int q = 0; q < 4; q++) {
            int m  = bm * 128 + r0 + q * 32;
            int b  = m / 49;
            int np = m - b * 49;
            int n  = np / 7;
            ar.p[q] = np - 7 * n;
            ar.g[q] = G_g + ((size_t)b * 147 + n * 7) * 256 + c8;
        }
    }

    uint32_t sA[3], sB[3], FB[3], EB[3];
#pragma unroll
    for (int s = 0; s < 3; s++) {
        sA[s] = sbase + s * (STG_H * 2);
        sB[s] = sbase + (3 + s) * (STG_H * 2);
        FB[s] = s2u(&mbar[s]);
        EB[s] = s2u(&mbar[3 + s]);
    }

    if (tid == 0) {
#pragma unroll
        for (int s = 0; s < 3; s++) {
            asm volatile("mbarrier.init.shared.b64 [%0], 256;" :: "r"(FB[s]) : "memory");
            asm volatile("mbarrier.init.shared.b64 [%0], 8;"   :: "r"(EB[s]) : "memory");
        }
    }
    __syncthreads();

    float acc[4][4][4];
#pragma unroll
    for (int a = 0; a < 4; a++)
#pragma unroll
        for (int b = 0; b < 4; b++)
#pragma unroll
            for (int c = 0; c < 4; c++) acc[a][b][c] = 0.f;

    // startup: chunks 0,1 -> stages 0,1
    produce(ar, Bg, sA[0], sB[0], 0, tid, FB[0]);
    produce(ar, Bg, sA[1], sB[1], 1, tid, FB[1]);

    const int a_row = wm * 64 + (lane & 15);
    const int a_kad = (lane >> 4) * 16;
    const int b_row = wn * 32 + ((lane >> 4) << 3) + (lane & 7);
    const int b_kad = ((lane >> 3) & 1) * 16;

#define CONSUME(cA, cB) do {                                                        \
    _Pragma("unroll")                                                               \
    for (int ks = 0; ks < 4; ks++) {                                                \
        const uint32_t kboff = (uint32_t)(ks * 32);                                 \
        uint32_t afr[4][4];                                                         \
        _Pragma("unroll")                                                           \
        for (int mi = 0; mi < 4; mi++) {                                            \
            uint32_t fa = (cA) + swz((uint32_t)((a_row + mi * 16) * 128 + kboff + a_kad)); \
            asm volatile("ldmatrix.sync.aligned.m8n8.x4.shared.b16 {%0,%1,%2,%3}, [%4];"   \
                         : "=r"(afr[mi][0]), "=r"(afr[mi][1]),                      \
                           "=r"(afr[mi][2]), "=r"(afr[mi][3]) : "r"(fa));           \
        }                                                                           \
        uint32_t bfr[2][4];                                                         \
        _Pragma("unroll")                                                           \
        for (int nb = 0; nb < 2; nb++) {                                            \
            uint32_t fb = (cB) + swz((uint32_t)((b_row + nb * 16) * 128 + kboff + b_kad)); \
            asm volatile("ldmatrix.sync.aligned.m8n8.x4.shared.b16 {%0,%1,%2,%3}, [%4];"   \
                         : "=r"(bfr[nb][0]), "=r"(bfr[nb][1]),                      \
                           "=r"(bfr[nb][2]), "=r"(bfr[nb][3]) : "r"(fb));           \
        }                                                                           \
        _Pragma("unroll")                                                           \
        for (int mi = 0; mi < 4; mi++)                                              \
            _Pragma("unroll")                                                       \
            for (int ni = 0; ni < 4; ni++) {                                        \
                const int nb = ni >> 1, hp = (ni & 1) * 2;                          \
                asm volatile(                                                       \
                    "mma.sync.aligned.m16n8k16.row.col.f32.f16.f16.f32 "            \
                    "{%0,%1,%2,%3}, {%4,%5,%6,%7}, {%8,%9}, {%0,%1,%2,%3};"         \
                    : "+f"(acc[mi][ni][0]), "+f"(acc[mi][ni][1]),                   \
                      "+f"(acc[mi][ni][2]), "+f"(acc[mi][ni][3])                    \
                    : "r"(afr[mi][0]), "r"(afr[mi][1]),                             \
                      "r"(afr[mi][2]), "r"(afr[mi][3]),                             \
                      "r"(bfr[nb][hp]), "r"(bfr[nb][hp + 1]));                      \
            }                                                                       \
    }                                                                               \
} while (0)

#define ARRIVE_EMPTY(s) do {                                                        \
    __syncwarp();                                                                   \
    if (lane == 0)                                                                  \
        asm volatile("mbarrier.arrive.shared.b64 _, [%0];" :: "r"(EB[s]) : "memory");\
} while (0)

    for (int u = 0; u < 12; u++) {
        const uint32_t up = (uint32_t)(u & 1);
        // ---- r=0: consume chunk 3u (stage 0); produce 3u+2 -> stage 2 ----
        MBWAIT(FB[0], up);
        CONSUME(sA[0], sB[0]);
        ARRIVE_EMPTY(0);
        if (u > 0) MBWAIT(EB[2], (uint32_t)((u - 1) & 1));
        produce(ar, Bg, sA[2], sB[2], 3 * u + 2, tid, FB[2]);
        // ---- r=1: consume chunk 3u+1 (stage 1); produce 3u+3 -> stage 0 ----
        MBWAIT(FB[1], up);
        CONSUME(sA[1], sB[1]);
        ARRIVE_EMPTY(1);
        if (u < 11) {
            MBWAIT(EB[0], up);
            produce(ar, Bg, sA[0], sB[0], 3 * u + 3, tid, FB[0]);
        }
        // ---- r=2: consume chunk 3u+2 (stage 2); produce 3u+4 -> stage 1 ----
        MBWAIT(FB[2], up);
        CONSUME(sA[2], sB[2]);
        ARRIVE_EMPTY(2);
        if (u < 11) {
            MBWAIT(EB[1], up);
            produce(ar, Bg, sA[1], sB[1], 3 * u + 4, tid, FB[1]);
        }
    }

    // ---- Epilogue: smem transpose -> coalesced stores ----
    __syncthreads();
    float* obuf = (float*)dsm;             // [128 i][132 m]
#pragma unroll
    for (int mi = 0; mi < 4; mi++) {
#pragma unroll
        for (int ni = 0; ni < 4; ni++) {
            int ml = wm * 64 + mi * 16 + (lane >> 2);
            int il = wn * 32 + ni * 8 + (lane & 3) * 2;
            obuf[il * 132 + ml]            = acc[mi][ni][0];
            obuf[(il + 1) * 132 + ml]      = acc[mi][ni][1];
            obuf[il * 132 + ml + 8]        = acc[mi][ni][2];
            obuf[(il + 1) * 132 + ml + 8]  = acc[mi][ni][3];
        }
    }
    __syncthreads();

    const int i_base = bn * 128;
    const int m_base = bm * 128;
    for (int idx = tid; idx < 128 * 128; idx += 256) {
        int il = idx >> 7, ml = idx & 127;
        int m  = m_base + ml;
        int b  = m / 49;
        int np = m - b * 49;
        out[(size_t)(b * NDIM + i_base + il) * 49 + np] = obuf[il * 132 + ml];
    }
}

// ---------------------------------------------------------------------------
extern "C" void kernel_launch(void* const* d_in, const int* in_sizes, int n_in,
                              void* d_out, int out_size) {
    const float* x = (const float*)d_in[0];   // (1024, 512, 7, 7)
    const float* W = (const float*)d_in[1];   // (256, 3, 3, 512)
    float* out = (float*)d_out;               // (1024, 512, 7, 7)

    cudaFuncSetAttribute(prep, cudaFuncAttributeMaxDynamicSharedMemorySize,
                         HW * XP2 * (int)sizeof(float));
    cudaFuncSetAttribute(gemm_f16, cudaFuncAttributeMaxDynamicSharedMemorySize, DSMEM);

    prep<<<2 * BATCH + 288, 512, HW * XP2 * sizeof(float)>>>(x, W);
    gemm_f16<<<dim3(NDIM / 128, MDIM / 128), 256, DSMEM>>>(out);
}

// round 16
// speedup vs baseline: 1.4355x; 1.0263x over previous
#include <cuda_runtime.h>
#include <cuda_fp16.h>
#include <cstdint>

#define BATCH 1024
#define CIN   512
#define HW    49
#define KDIM  2304          // 9 * 256
#define MDIM  50176         // 1024 * 49
#define NDIM  512

__device__ __align__(16) __half G_g[(size_t)BATCH * 3 * HW * 256];   // 77 MB
__device__ __align__(16) __half Whn_g[(size_t)NDIM * KDIM];          // [i][kk] K-major

// ---------------------------------------------------------------------------
__device__ __forceinline__ uint32_t s2u(const void* p) {
    uint32_t a;
    asm("{ .reg .u64 t; cvta.to.shared.u64 t, %1; cvt.u32.u64 %0, t; }" : "=r"(a) : "l"(p));
    return a;
}
__device__ __forceinline__ uint32_t swz(uint32_t o) { return o ^ ((o >> 3) & 0x70); }

#define MBWAIT(addr, par) do {                                                 \
    asm volatile("{\n\t.reg .pred P1;\n\t"                                     \
        "WL%=:\n\t"                                                            \
        "mbarrier.try_wait.parity.acquire.cta.shared::cta.b64 P1, [%0], %1, 0x989680;\n\t" \
        "@P1 bra.uni WD%=;\n\t"                                                \
        "bra.uni WL%=;\n\t"                                                    \
        "WD%=:\n\t}"                                                           \
        :: "r"(addr), "r"((uint32_t)(par)) : "memory");                        \
} while (0)

// ---------------------------------------------------------------------------
// Phase 1 (merged): blocks [0, 4096) build G (4 blocks/batch, quarter
// channels -> 26KB stage, 4 blocks/SM); blocks [4096, 4384) transpose W.
//
// Block (b, q): stages channels [q*64, q*64+64) (group0 -> cc 0..63) and
// [256+q*64, +64) (group1 -> cc 64..127) as xs[hw][cc], row pitch 132.
// Staging via float4 (slice bases 16B-aligned: q*3136 and 12544+q*3136).
// ---------------------------------------------------------------------------
#define XPQ 132
#define GWORKQ (3 * HW * 8)   // 1176 items per block

__global__ __launch_bounds__(512, 4) void prep(const float* __restrict__ x,
                                               const float* __restrict__ W) {
    extern __shared__ float sm[];

    if (blockIdx.x < 4 * BATCH) {
        const int b = blockIdx.x >> 2;
        const int q = blockIdx.x & 3;
        const float* xb = x + (size_t)b * CIN * HW;

        // stage two 64-channel slices (each 3136 floats, 16B-aligned base)
#pragma unroll
        for (int g = 0; g < 2; g++) {
            const float4* src = (const float4*)(xb + (g ? (49 * 256 + q * 3136)
                                                       : (q * 3136)));
            const int ccbase = g * 64;
            for (int v = threadIdx.x; v < 3136 / 4; v += blockDim.x) {
                float4 f = src[v];
                int e = v * 4;
#pragma unroll
                for (int s = 0; s < 4; s++) {
                    int ee = e + s;
                    int c  = ee / HW;
                    int hw = ee - c * HW;
                    float val = (s == 0) ? f.x : (s == 1) ? f.y : (s == 2) ? f.z : f.w;
                    sm[hw * XPQ + ccbase + c] = val;
                }
            }
        }
        __syncthreads();

        uint4* gout = (uint4*)(G_g + (size_t)b * 3 * HW * 256);

        for (int base = threadIdx.x; base < GWORKQ; base += 1024) {
            int idx0 = base;
            int idx1 = base + 512;
            const bool has1 = (idx1 < GWORKQ);

            int l8_0 = idx0 & 7,  rr0 = idx0 >> 3;
            int l8_1 = idx1 & 7,  rr1 = idx1 >> 3;

            int j0 = rr0 / 49, nw0 = rr0 - j0 * 49, n0 = nw0 / 7, w0 = nw0 - 7 * n0;
            int j1 = rr1 / 49, nw1 = rr1 - j1 * 49, n1 = nw1 / 7, w1 = nw1 - 7 * n1;

            int hb0 = n0 + j0 - 1, ha0 = ((n0 + 6) % 7) + j0 - 1;
            int hb1 = n1 + j1 - 1, ha1 = ((n1 + 6) % 7) + j1 - 1;
            bool bv0 = (hb0 >= 0) && (hb0 < 7), av0 = (ha0 >= 0) && (ha0 < 7);
            bool bv1 = has1 && (hb1 >= 0) && (hb1 < 7);
            bool av1 = has1 && (ha1 >= 0) && (ha1 < 7);

            const float4* pa0 = (const float4*)(sm + (ha0 * 7 + w0) * XPQ + 64 + l8_0 * 8);
            const float4* pb0 = (const float4*)(sm + (hb0 * 7 + w0) * XPQ + l8_0 * 8);
            const float4* pa1 = (const float4*)(sm + (ha1 * 7 + w1) * XPQ + 64 + l8_1 * 8);
            const float4* pb1 = (const float4*)(sm + (hb1 * 7 + w1) * XPQ + l8_1 * 8);

            float4 a00 = {0,0,0,0}, a01 = {0,0,0,0}, b00 = {0,0,0,0}, b01 = {0,0,0,0};
            float4 a10 = {0,0,0,0}, a11 = {0,0,0,0}, b10 = {0,0,0,0}, b11 = {0,0,0,0};
            if (av0) { a00 = pa0[0]; a01 = pa0[1]; }
            if (bv0) { b00 = pb0[0]; b01 = pb0[1]; }
            if (av1) { a10 = pa1[0]; a11 = pa1[1]; }
            if (bv1) { b10 = pb1[0]; b11 = pb1[1]; }

            {
                __half2 p0 = __floats2half2_rn(a00.x + b00.x, a00.y + b00.y);
                __half2 p1 = __floats2half2_rn(a00.z + b00.z, a00.w + b00.w);
                __half2 p2 = __floats2half2_rn(a01.x + b01.x, a01.y + b01.y);
                __half2 p3 = __floats2half2_rn(a01.z + b01.z, a01.w + b01.w);
                uint4 o;
                o.x = *reinterpret_cast<uint32_t*>(&p0);
                o.y = *reinterpret_cast<uint32_t*>(&p1);
                o.z = *reinterpret_cast<uint32_t*>(&p2);
                o.w = *reinterpret_cast<uint32_t*>(&p3);
                gout[rr0 * 32 + q * 8 + l8_0] = o;
            }
            if (has1) {
                __half2 p0 = __floats2half2_rn(a10.x + b10.x, a10.y + b10.y);
                __half2 p1 = __floats2half2_rn(a10.z + b10.z, a10.w + b10.w);
                __half2 p2 = __floats2half2_rn(a11.x + b11.x, a11.y + b11.y);
                __half2 p3 = __floats2half2_rn(a11.z + b11.z, a11.w + b11.w);
                uint4 o;
                o.x = *reinterpret_cast<uint32_t*>(&p0);
                o.y = *reinterpret_cast<uint32_t*>(&p1);
                o.z = *reinterpret_cast<uint32_t*>(&p2);
                o.w = *reinterpret_cast<uint32_t*>(&p3);
                gout[rr1 * 32 + q * 8 + l8_1] = o;
            }
        }
    } else {
        float* tile = sm;                       // [64][65]
        const int bid2 = blockIdx.x - 4 * BATCH;
        const int jk = bid2 / 32;
        const int r  = bid2 - jk * 32;
        const int lt = r >> 3;
        const int it = r & 7;

        for (int i = threadIdx.x; i < 64 * 64; i += blockDim.x) {
            int ll = i >> 6, ii = i & 63;
            tile[ll * 65 + ii] = W[((size_t)(lt * 64 + ll) * 9 + jk) * NDIM + it * 64 + ii];
        }
        __syncthreads();

        __half2* out2 = (__half2*)Whn_g;
        for (int i = threadIdx.x; i < 64 * 32; i += blockDim.x) {
            int ii = i >> 5, l2 = i & 31;
            float v0 = tile[(l2 * 2) * 65 + ii];
            float v1 = tile[(l2 * 2 + 1) * 65 + ii];
            out2[(size_t)(it * 64 + ii) * (KDIM / 2) + jk * 128 + lt * 32 + l2] =
                __floats2half2_rn(v0, v1);
        }
    }
}

// ---------------------------------------------------------------------------
// Phase 2: fused-im2col GEMM, mbarrier-decoupled pipeline (R14, unchanged).
// ---------------------------------------------------------------------------
#define BK 64
#define NC (KDIM / BK)        // 36
#define STG_H 8192
#define DSMEM (3 * 2 * STG_H * 2 + 256)

struct ARow {
    const __half* g[4];
    int p[4];
};

__device__ __forceinline__ void produce(
    const ARow& ar, const __half* __restrict__ Bg,
    uint32_t sA, uint32_t sB, int chunk, int tid, uint32_t mb_full)
{
    const int jk = chunk >> 2;
    const int l0 = (chunk & 3) << 6;
    const int j  = (jk * 11) >> 5;
    const int k  = jk - 3 * j;
    const int off0 = j * (49 * 256) + l0;
    const int r0 = tid >> 3;
    const int c16 = (tid & 7) * 16;
#pragma unroll
    for (int q = 0; q < 4; q++) {
        const int p = ar.p[q];
        int w2 = p + k + 5; if (w2 >= 7) w2 -= 7;
        const uint32_t vsz = ((unsigned)(p + k - 1) <= 6u) ? 16u : 0u;
        const uint32_t dst = sA + swz((uint32_t)((r0 + q * 32) * 128 + c16));
        const __half* src = ar.g[q] + off0 + w2 * 256;
        asm volatile("cp.async.cg.shared.global [%0], [%1], 16, %2;"
                     :: "r"(dst), "l"(src), "r"(vsz));
    }
    const int k0 = chunk * BK;
#pragma unroll
    for (int q = 0; q < 4; q++) {
        int id = tid + q * 256;
        int r = id >> 3, c = id & 7;
        asm volatile("cp.async.cg.shared.global [%0], [%1], 16;"
                     :: "r"(sB + swz((uint32_t)(r * 128 + c * 16))),
                        "l"(Bg + (size_t)r * KDIM + k0 + c * 8));
    }
    asm volatile("cp.async.mbarrier.arrive.noinc.shared.b64 [%0];"
                 :: "r"(mb_full) : "memory");
}

__global__ __launch_bounds__(256, 2) void gemm_f16(float* __restrict__ out) {
    extern __shared__ char dsm[];
    __shared__ __align__(8) uint64_t mbar[6];   // full[0..2], empty[0..2]
    const uint32_t sbase = (s2u(dsm) + 127) & ~127u;

    const int bn   = blockIdx.x;
    const int bm   = blockIdx.y;
    const int tid  = threadIdx.x;
    const int wid  = tid >> 5;
    const int lane = tid & 31;
    const int wm   = wid >> 2;
    const int wn   = wid & 3;

    const __half* Bg = Whn_g + (size_t)bn * 128 * KDIM;

    ARow ar;
    {
        const int r0 = tid >> 3;
        const int c8 = (tid & 7) * 8;
#pragma unroll
        for (int q = 0; q < 4; q++) {
            int m  = bm * 128 + r0 + q * 32;
            int b  = m / 49;
            int np = m - b * 49;
            int n  = np / 7;
            ar.p[q] = np - 7 * n;
            ar.g[q] = G_g + ((size_t)b * 147 + n * 7) * 256 + c8;
        }
    }

    uint32_t sA[3], sB[3], FB[3], EB[3];
#pragma unroll
    for (int s = 0; s < 3; s++) {
        sA[s] = sbase + s * (STG_H * 2);
        sB[s] = sbase + (3 + s) * (STG_H * 2);
        FB[s] = s2u(&mbar[s]);
        EB[s] = s2u(&mbar[3 + s]);
    }

    if (tid == 0) {
#pragma unroll
        for (int s = 0; s < 3; s++) {
            asm volatile("mbarrier.init.shared.b64 [%0], 256;" :: "r"(FB[s]) : "memory");
            asm volatile("mbarrier.init.shared.b64 [%0], 8;"   :: "r"(EB[s]) : "memory");
        }
    }
    __syncthreads();

    float acc[4][4][4];
#pragma unroll
    for (int a = 0; a < 4; a++)
#pragma unroll
        for (int b = 0; b < 4; b++)
#pragma unroll
            for (int c = 0; c < 4; c++) acc[a][b][c] = 0.f;

    produce(ar, Bg, sA[0], sB[0], 0, tid, FB[0]);
    produce(ar, Bg, sA[1], sB[1], 1, tid, FB[1]);

    const int a_row = wm * 64 + (lane & 15);
    const int a_kad = (lane >> 4) * 16;
    const int b_row = wn * 32 + ((lane >> 4) << 3) + (lane & 7);
    const int b_kad = ((lane >> 3) & 1) * 16;

#define CONSUME(cA, cB) do {                                                        \
    _Pragma("unroll")                                                               \
    for (int ks = 0; ks < 4; ks++) {                                                \
        const uint32_t kboff = (uint32_t)(ks * 32);                                 \
        uint32_t afr[4][4];                                                         \
        _Pragma("unroll")                                                           \
        for (int mi = 0; mi < 4; mi++) {                                            \
            uint32_t fa = (cA) + swz((uint32_t)((a_row + mi * 16) * 128 + kboff + a_kad)); \
            asm volatile("ldmatrix.sync.aligned.m8n8.x4.shared.b16 {%0,%1,%2,%3}, [%4];"   \
                         : "=r"(afr[mi][0]), "=r"(afr[mi][1]),                      \
                           "=r"(afr[mi][2]), "=r"(afr[mi][3]) : "r"(fa));           \
        }                                                                           \
        uint32_t bfr[2][4];                                                         \
        _Pragma("unroll")                                                           \
        for (int nb = 0; nb < 2; nb++) {                                            \
            uint32_t fb = (cB) + swz((uint32_t)((b_row + nb * 16) * 128 + kboff + b_kad)); \
            asm volatile("ldmatrix.sync.aligned.m8n8.x4.shared.b16 {%0,%1,%2,%3}, [%4];"   \
                         : "=r"(bfr[nb][0]), "=r"(bfr[nb][1]),                      \
                           "=r"(bfr[nb][2]), "=r"(bfr[nb][3]) : "r"(fb));           \
        }                                                                           \
        _Pragma("unroll")                                                           \
        for (int mi = 0; mi < 4; mi++)                                              \
            _Pragma("unroll")                                                       \
            for (int ni = 0; ni < 4; ni++) {                                        \
                const int nb = ni >> 1, hp = (ni & 1) * 2;                          \
                asm volatile(                                                       \
                    "mma.sync.aligned.m16n8k16.row.col.f32.f16.f16.f32 "            \
                    "{%0,%1,%2,%3}, {%4,%5,%6,%7}, {%8,%9}, {%0,%1,%2,%3};"         \
                    : "+f"(acc[mi][ni][0]), "+f"(acc[mi][ni][1]),                   \
                      "+f"(acc[mi][ni][2]), "+f"(acc[mi][ni][3])                    \
                    : "r"(afr[mi][0]), "r"(afr[mi][1]),                             \
                      "r"(afr[mi][2]), "r"(afr[mi][3]),                             \
                      "r"(bfr[nb][hp]), "r"(bfr[nb][hp + 1]));                      \
            }                                                                       \
    }                                                                               \
} while (0)

#define ARRIVE_EMPTY(s) do {                                                        \
    __syncwarp();                                                                   \
    if (lane == 0)                                                                  \
        asm volatile("mbarrier.arrive.shared.b64 _, [%0];" :: "r"(EB[s]) : "memory");\
} while (0)

    for (int u = 0; u < 12; u++) {
        const uint32_t up = (uint32_t)(u & 1);
        MBWAIT(FB[0], up);
        CONSUME(sA[0], sB[0]);
        ARRIVE_EMPTY(0);
        if (u > 0) MBWAIT(EB[2], (uint32_t)((u - 1) & 1));
        produce(ar, Bg, sA[2], sB[2], 3 * u + 2, tid, FB[2]);
        MBWAIT(FB[1], up);
        CONSUME(sA[1], sB[1]);
        ARRIVE_EMPTY(1);
        if (u < 11) {
            MBWAIT(EB[0], up);
            produce(ar, Bg, sA[0], sB[0], 3 * u + 3, tid, FB[0]);
        }
        MBWAIT(FB[2], up);
        CONSUME(sA[2], sB[2]);
        ARRIVE_EMPTY(2);
        if (u < 11) {
            MBWAIT(EB[1], up);
            produce(ar, Bg, sA[1], sB[1], 3 * u + 4, tid, FB[1]);
        }
    }

    // ---- Epilogue: smem transpose -> coalesced stores ----
    __syncthreads();
    float* obuf = (float*)dsm;             // [128 i][132 m]
#pragma unroll
    for (int mi = 0; mi < 4; mi++) {
#pragma unroll
        for (int ni = 0; ni < 4; ni++) {
            int ml = wm * 64 + mi * 16 + (lane >> 2);
            int il = wn * 32 + ni * 8 + (lane & 3) * 2;
            obuf[il * 132 + ml]            = acc[mi][ni][0];
            obuf[(il + 1) * 132 + ml]      = acc[mi][ni][1];
            obuf[il * 132 + ml + 8]        = acc[mi][ni][2];
            obuf[(il + 1) * 132 + ml + 8]  = acc[mi][ni][3];
        }
    }
    __syncthreads();

    const int i_base = bn * 128;
    const int m_base = bm * 128;
    for (int idx = tid; idx < 128 * 128; idx += 256) {
        int il = idx >> 7, ml = idx & 127;
        int m  = m_base + ml;
        int b  = m / 49;
        int np = m - b * 49;
        out[(size_t)(b * NDIM + i_base + il) * 49 + np] = obuf[il * 132 + ml];
    }
}

// ---------------------------------------------------------------------------
extern "C" void kernel_launch(void* const* d_in, const int* in_sizes, int n_in,
                              void* d_out, int out_size) {
    const float* x = (const float*)d_in[0];   // (1024, 512, 7, 7)
    const float* W = (const float*)d_in[1];   // (256, 3, 3, 512)
    float* out = (float*)d_out;               // (1024, 512, 7, 7)

    cudaFuncSetAttribute(prep, cudaFuncAttributeMaxDynamicSharedMemorySize,
                         HW * XPQ * (int)sizeof(float));
    cudaFuncSetAttribute(gemm_f16, cudaFuncAttributeMaxDynamicSharedMemorySize, DSMEM);

    prep<<<4 * BATCH + 288, 512, HW * XPQ * sizeof(float)>>>(x, W);
    gemm_f16<<<dim3(NDIM / 128, MDIM / 128), 256, DSMEM>>>(out);
}